// round 1
// baseline (speedup 1.0000x reference)
#include <cuda_runtime.h>
#include <cuda_bf16.h>
#include <cstdint>

#define D            128
#define S            16
#define WARPS_PB     8
#define ITEM_TILE    4
#define ITEMS_PB     (WARPS_PB * ITEM_TILE)   // 32
#define BLOCK_THREADS (WARPS_PB * 32)         // 256

// Shared layout: W [128*128 floats] + per-warp x buffers [WARPS_PB * ITEM_TILE * D]
#define SMEM_FLOATS (D * D + WARPS_PB * ITEM_TILE * D)
#define SMEM_BYTES  (SMEM_FLOATS * 4)

__global__ __launch_bounds__(BLOCK_THREADS, 2)
void kgcn_kernel(const int* __restrict__ u,
                 const int* __restrict__ v,
                 const int* __restrict__ adj_ent,
                 const int* __restrict__ adj_rel,
                 const float* __restrict__ usr,
                 const float* __restrict__ ent,
                 const float* __restrict__ rel,
                 const float* __restrict__ W,
                 const float* __restrict__ bias,
                 float* __restrict__ out,
                 int B)
{
    extern __shared__ float smem[];
    float* Wsh = smem;                    // 16384 floats
    float* xs  = smem + D * D;            // WARPS_PB * ITEM_TILE * D floats

    const int tid  = threadIdx.x;
    const int lane = tid & 31;
    const int wid  = tid >> 5;

    // ---- stage W into shared (row-major, W[i*128 + j]) ----
    {
        const float4* Wg4 = (const float4*)W;
        float4* Ws4 = (float4*)Wsh;
        #pragma unroll
        for (int k = 0; k < (D * D / 4) / BLOCK_THREADS; k++) {
            int i = tid + k * BLOCK_THREADS;
            Ws4[i] = Wg4[i];
        }
    }
    __syncthreads();

    float* xw = xs + wid * (ITEM_TILE * D);

    const int base = (blockIdx.x * WARPS_PB + wid) * ITEM_TILE;

    const float4* usr4 = (const float4*)usr;
    const float4* ent4 = (const float4*)ent;
    const float4* rel4 = (const float4*)rel;

    // Lane owns dims j = lane*4 + m (float4 per lane) -- consistent everywhere.
    float4 ue[ITEM_TILE];    // user embedding
    float4 mg[ITEM_TILE];    // attention-weighted neighbor message

    #pragma unroll
    for (int t = 0; t < ITEM_TILE; t++) {
        int item = base + t;
        int cit  = item < B ? item : (B - 1);   // clamp (deterministic)
        const int iu = u[cit];
        const int iv = v[cit];

        const float4 uex = usr4[(size_t)iu * 32 + lane];
        ue[t] = uex;
        const float4 rp = ent4[(size_t)iv * 32 + lane];

        // -- attention scores: sc[s] = dot(u_emb, rel_table[adj_rel[v,s]]) --
        float sc[S];
        #pragma unroll
        for (int s = 0; s < S; s++) {
            int ridx = __ldg(&adj_rel[iv * S + s]);
            float4 r4 = rel4[(size_t)ridx * 32 + lane];
            float p = uex.x * r4.x + uex.y * r4.y + uex.z * r4.z + uex.w * r4.w;
            #pragma unroll
            for (int o = 16; o > 0; o >>= 1)
                p += __shfl_xor_sync(0xffffffffu, p, o);
            sc[s] = p;   // replicated in all lanes
        }

        // -- softmax over S --
        float mx = sc[0];
        #pragma unroll
        for (int s = 1; s < S; s++) mx = fmaxf(mx, sc[s]);
        float sum = 0.f;
        #pragma unroll
        for (int s = 0; s < S; s++) { sc[s] = __expf(sc[s] - mx); sum += sc[s]; }
        const float inv = __frcp_rn(sum);

        // -- message: msg = sum_s attn[s] * ent_table[adj_ent[v,s]] --
        float4 msg = make_float4(0.f, 0.f, 0.f, 0.f);
        #pragma unroll
        for (int s = 0; s < S; s++) {
            int eidx = __ldg(&adj_ent[iv * S + s]);
            float4 e4 = ent4[(size_t)eidx * 32 + lane];
            float a = sc[s] * inv;
            msg.x = fmaf(a, e4.x, msg.x);
            msg.y = fmaf(a, e4.y, msg.y);
            msg.z = fmaf(a, e4.z, msg.z);
            msg.w = fmaf(a, e4.w, msg.w);
        }
        mg[t] = msg;

        // x0 = msg + rep0  -> shared (for GEMV broadcast reads)
        float4 x0 = make_float4(msg.x + rp.x, msg.y + rp.y, msg.z + rp.z, msg.w + rp.w);
        ((float4*)(xw + t * D))[lane] = x0;
    }
    __syncwarp();

    const float4 b4 = ((const float4*)bias)[lane];
    float acc[ITEM_TILE][4];

    // ---- 2 iterations: rep = relu((msg + rep) @ W + b) ----
    #pragma unroll
    for (int iter = 0; iter < 2; iter++) {
        #pragma unroll
        for (int t = 0; t < ITEM_TILE; t++) {
            acc[t][0] = b4.x; acc[t][1] = b4.y; acc[t][2] = b4.z; acc[t][3] = b4.w;
        }

        #pragma unroll 8
        for (int i = 0; i < D; i++) {
            const float4 w4 = ((const float4*)Wsh)[i * 32 + lane];  // W[i][lane*4..+3]
            #pragma unroll
            for (int t = 0; t < ITEM_TILE; t++) {
                const float xi = xw[t * D + i];   // broadcast
                acc[t][0] = fmaf(xi, w4.x, acc[t][0]);
                acc[t][1] = fmaf(xi, w4.y, acc[t][1]);
                acc[t][2] = fmaf(xi, w4.z, acc[t][2]);
                acc[t][3] = fmaf(xi, w4.w, acc[t][3]);
            }
        }

        if (iter == 0) {
            __syncwarp();   // all lanes done reading xw before overwrite
            #pragma unroll
            for (int t = 0; t < ITEM_TILE; t++) {
                float4 xn;
                xn.x = mg[t].x + fmaxf(acc[t][0], 0.f);
                xn.y = mg[t].y + fmaxf(acc[t][1], 0.f);
                xn.z = mg[t].z + fmaxf(acc[t][2], 0.f);
                xn.w = mg[t].w + fmaxf(acc[t][3], 0.f);
                ((float4*)(xw + t * D))[lane] = xn;
            }
            __syncwarp();
        }
    }

    // ---- final: sigmoid(dot(u_emb, relu(acc))) ----
    #pragma unroll
    for (int t = 0; t < ITEM_TILE; t++) {
        float p = ue[t].x * fmaxf(acc[t][0], 0.f)
                + ue[t].y * fmaxf(acc[t][1], 0.f)
                + ue[t].z * fmaxf(acc[t][2], 0.f)
                + ue[t].w * fmaxf(acc[t][3], 0.f);
        #pragma unroll
        for (int o = 16; o > 0; o >>= 1)
            p += __shfl_xor_sync(0xffffffffu, p, o);
        int item = base + t;
        if (lane == 0 && item < B)
            out[item] = 1.f / (1.f + __expf(-p));
    }
}

extern "C" void kernel_launch(void* const* d_in, const int* in_sizes, int n_in,
                              void* d_out, int out_size)
{
    const int*   u       = (const int*)d_in[0];
    const int*   v       = (const int*)d_in[1];
    const int*   adj_ent = (const int*)d_in[2];
    const int*   adj_rel = (const int*)d_in[3];
    const float* usr     = (const float*)d_in[4];
    const float* ent     = (const float*)d_in[5];
    const float* rel     = (const float*)d_in[6];
    const float* W       = (const float*)d_in[7];
    const float* bias    = (const float*)d_in[8];
    float* out = (float*)d_out;

    const int B = in_sizes[0];

    static bool attr_set = false;
    if (!attr_set) {
        cudaFuncSetAttribute(kgcn_kernel,
                             cudaFuncAttributeMaxDynamicSharedMemorySize,
                             SMEM_BYTES);
        attr_set = true;
    }

    dim3 grid((B + ITEMS_PB - 1) / ITEMS_PB);
    kgcn_kernel<<<grid, BLOCK_THREADS, SMEM_BYTES>>>(
        u, v, adj_ent, adj_rel, usr, ent, rel, W, bias, out, B);
}